// round 1
// baseline (speedup 1.0000x reference)
#include <cuda_runtime.h>
#include <cuda_bf16.h>

#define N_TOK 2048
#define D_DIM 768
#define H_HEADS 12
#define Y_DIM 64
#define HY 768              // H*Y
#define BETA 0.125f         // 1/sqrt(64)

// Scratch (allocation-free rule: device globals)
__device__ float g_Q[N_TOK * HY];
__device__ float g_K[N_TOK * HY];
__device__ float g_partial[H_HEADS * (N_TOK / 64)];   // 12*32 = 384 per-block LSE sums

// ---------------------------------------------------------------------------
// Projection: Out[n][j] = sum_d G[n][d] * W[j][d]
// G: [2048, 768] row-major; W: [768, 768] row-major (j = h*64+y)
// 64x64 C tile, k-tile 16, 256 threads, 4x4 register blocking.
// ---------------------------------------------------------------------------
__global__ __launch_bounds__(256) void proj_kernel(const float* __restrict__ G,
                                                   const float* __restrict__ W,
                                                   float* __restrict__ Out) {
    __shared__ float As[16][68];   // As[kk][m]  (padded rows: 68 floats, float4-aligned)
    __shared__ float Bs[16][68];   // Bs[kk][n]

    const int bm = blockIdx.y * 64;   // token rows
    const int bn = blockIdx.x * 64;   // output cols (h*64+y)
    const int tid = threadIdx.x;
    const int tx = tid & 15;
    const int ty = tid >> 4;

    float acc[4][4];
#pragma unroll
    for (int r = 0; r < 4; r++)
#pragma unroll
        for (int c = 0; c < 4; c++) acc[r][c] = 0.f;

    const int li = tid >> 2;            // 0..63 : row within tile
    const int lj = (tid & 3) * 4;       // 0,4,8,12 : d-offset

    for (int kt = 0; kt < D_DIM; kt += 16) {
        float4 av = *(const float4*)&G[(size_t)(bm + li) * D_DIM + kt + lj];
        float4 bv = *(const float4*)&W[(size_t)(bn + li) * D_DIM + kt + lj];
        As[lj + 0][li] = av.x; As[lj + 1][li] = av.y;
        As[lj + 2][li] = av.z; As[lj + 3][li] = av.w;
        Bs[lj + 0][li] = bv.x; Bs[lj + 1][li] = bv.y;
        Bs[lj + 2][li] = bv.z; Bs[lj + 3][li] = bv.w;
        __syncthreads();

#pragma unroll
        for (int kk = 0; kk < 16; kk++) {
            float4 a = *(const float4*)&As[kk][ty * 4];
            float4 b = *(const float4*)&Bs[kk][tx * 4];
            acc[0][0] += a.x * b.x; acc[0][1] += a.x * b.y; acc[0][2] += a.x * b.z; acc[0][3] += a.x * b.w;
            acc[1][0] += a.y * b.x; acc[1][1] += a.y * b.y; acc[1][2] += a.y * b.z; acc[1][3] += a.y * b.w;
            acc[2][0] += a.z * b.x; acc[2][1] += a.z * b.y; acc[2][2] += a.z * b.z; acc[2][3] += a.z * b.w;
            acc[3][0] += a.w * b.x; acc[3][1] += a.w * b.y; acc[3][2] += a.w * b.z; acc[3][3] += a.w * b.w;
        }
        __syncthreads();
    }

#pragma unroll
    for (int r = 0; r < 4; r++) {
        float* orow = &Out[(size_t)(bm + ty * 4 + r) * HY + bn + tx * 4];
        orow[0] = acc[r][0]; orow[1] = acc[r][1]; orow[2] = acc[r][2]; orow[3] = acc[r][3];
    }
}

// ---------------------------------------------------------------------------
// Attention LSE: for head h, q rows [q0, q0+64): compute sum over those rows of
// logsumexp_k( beta * <Q[q,h,:], K[k,h,:]> ), online-softmax over k tiles of 64.
// 256 threads = 8 warps; warp w owns q rows w*8..w*8+7; lane handles k cols
// {lane, lane+32} of the current tile.
// ---------------------------------------------------------------------------
__global__ __launch_bounds__(256) void attn_lse_kernel() {
    __shared__ float Qs[64][65];   // Qs[y][q_local]
    __shared__ float Ks[64][65];   // Ks[y][k_local]
    __shared__ float warp_sums[8];

    const int h  = blockIdx.y;
    const int q0 = blockIdx.x * 64;
    const int tid  = threadIdx.x;
    const int lane = tid & 31;
    const int wid  = tid >> 5;
    const int r0   = wid * 8;      // first q row owned by this warp

    // Load Q tile once: Qs[y][nl] = g_Q[(q0+nl)*768 + h*64 + y]
#pragma unroll
    for (int t = 0; t < 16; t++) {
        int i = tid + t * 256;          // 0..4095
        int nl = i >> 6;
        int y  = i & 63;
        Qs[y][nl] = g_Q[(size_t)(q0 + nl) * HY + h * Y_DIM + y];
    }
    __syncthreads();

    float m[8], s[8];
#pragma unroll
    for (int r = 0; r < 8; r++) { m[r] = -3.0e38f; s[r] = 0.f; }

    for (int kt = 0; kt < N_TOK; kt += 64) {
#pragma unroll
        for (int t = 0; t < 16; t++) {
            int i = tid + t * 256;
            int nl = i >> 6;
            int y  = i & 63;
            Ks[y][nl] = g_K[(size_t)(kt + nl) * HY + h * Y_DIM + y];
        }
        __syncthreads();

        float acc0[8], acc1[8];
#pragma unroll
        for (int r = 0; r < 8; r++) { acc0[r] = 0.f; acc1[r] = 0.f; }

#pragma unroll 4
        for (int d = 0; d < 64; d++) {
            float kv0 = Ks[d][lane];
            float kv1 = Ks[d][lane + 32];
#pragma unroll
            for (int r = 0; r < 8; r++) {
                float qv = Qs[d][r0 + r];
                acc0[r] += qv * kv0;
                acc1[r] += qv * kv1;
            }
        }

        // online softmax update, one warp reduction pair per row
#pragma unroll
        for (int r = 0; r < 8; r++) {
            float v0 = BETA * acc0[r];
            float v1 = BETA * acc1[r];
            float lm = fmaxf(v0, v1);
#pragma unroll
            for (int off = 16; off > 0; off >>= 1)
                lm = fmaxf(lm, __shfl_xor_sync(0xffffffffu, lm, off));
            float mn = fmaxf(m[r], lm);
            float p = __expf(v0 - mn) + __expf(v1 - mn);
#pragma unroll
            for (int off = 16; off > 0; off >>= 1)
                p += __shfl_xor_sync(0xffffffffu, p, off);
            s[r] = s[r] * __expf(m[r] - mn) + p;
            m[r] = mn;
        }
        __syncthreads();
    }

    // per-warp LSE sum over its 8 rows (all lanes hold identical m/s)
    if (lane == 0) {
        float acc = 0.f;
#pragma unroll
        for (int r = 0; r < 8; r++) acc += m[r] + logf(s[r]);
        warp_sums[wid] = acc;
    }
    __syncthreads();
    if (tid == 0) {
        float b = 0.f;
#pragma unroll
        for (int w = 0; w < 8; w++) b += warp_sums[w];
        g_partial[blockIdx.y * (N_TOK / 64) + blockIdx.x] = b;
    }
}

// ---------------------------------------------------------------------------
// Deterministic final reduction of 384 partials -> out[0] = -8 * sum
// ---------------------------------------------------------------------------
__global__ __launch_bounds__(128) void final_reduce_kernel(float* __restrict__ out) {
    __shared__ float sh[128];
    const int tid = threadIdx.x;
    float a = 0.f;
#pragma unroll
    for (int t = 0; t < 3; t++) a += g_partial[tid + t * 128];
    sh[tid] = a;
    __syncthreads();
    for (int off = 64; off > 0; off >>= 1) {
        if (tid < off) sh[tid] += sh[tid + off];
        __syncthreads();
    }
    if (tid == 0) out[0] = -8.0f * sh[0];
}

// ---------------------------------------------------------------------------
extern "C" void kernel_launch(void* const* d_in, const int* in_sizes, int n_in,
                              void* d_out, int out_size) {
    const float* g  = (const float*)d_in[0];
    const float* Wq = (const float*)d_in[1];
    const float* Wk = (const float*)d_in[2];
    float* out = (float*)d_out;

    float* Qb; cudaGetSymbolAddress((void**)&Qb, g_Q);
    float* Kb; cudaGetSymbolAddress((void**)&Kb, g_K);

    dim3 pgrid(HY / 64, N_TOK / 64);   // (12, 32)
    proj_kernel<<<pgrid, 256>>>(g, Wq, Qb);
    proj_kernel<<<pgrid, 256>>>(g, Wk, Kb);

    dim3 agrid(N_TOK / 64, H_HEADS);   // (32, 12)
    attn_lse_kernel<<<agrid, 256>>>();

    final_reduce_kernel<<<1, 128>>>(out);
}

// round 4
// speedup vs baseline: 2.4156x; 2.4156x over previous
#include <cuda_runtime.h>
#include <cstdint>
#include <math.h>

#define N_TOK 2048
#define D_DIM 768
#define HY 768
#define H_HEADS 12

// Scratch (allocation-free rule: device globals)
__device__ float g_Q[N_TOK * HY];       // scaled by beta*log2e
__device__ float g_K[N_TOK * HY];
__device__ float g_partial[H_HEADS * 32];   // 12*32 = 384 per-block LSE2 sums

// ---------------------------------------------------------------------------
__device__ __forceinline__ uint32_t smem_u32(const void* p) {
    uint32_t a;
    asm("{ .reg .u64 t; cvta.to.shared.u64 t, %1; cvt.u32.u64 %0, t; }"
        : "=r"(a) : "l"(p));
    return a;
}
__device__ __forceinline__ uint32_t f2tf(float x) {   // round-to-nearest tf32
    uint32_t r;
    asm("cvt.rna.tf32.f32 %0, %1;" : "=r"(r) : "f"(x));
    return r;
}
__device__ __forceinline__ void ldmx4(uint32_t r[4], uint32_t addr) {
    asm volatile("ldmatrix.sync.aligned.m8n8.x4.shared.b16 {%0,%1,%2,%3}, [%4];"
                 : "=r"(r[0]), "=r"(r[1]), "=r"(r[2]), "=r"(r[3]) : "r"(addr));
}
__device__ __forceinline__ void mma_tf32(float c[4], const uint32_t a[4],
                                         uint32_t b0, uint32_t b1) {
    asm volatile(
        "mma.sync.aligned.m16n8k8.row.col.f32.tf32.tf32.f32 "
        "{%0,%1,%2,%3}, {%4,%5,%6,%7}, {%8,%9}, {%0,%1,%2,%3};"
        : "+f"(c[0]), "+f"(c[1]), "+f"(c[2]), "+f"(c[3])
        : "r"(a[0]), "r"(a[1]), "r"(a[2]), "r"(a[3]), "r"(b0), "r"(b1));
}

// ---------------------------------------------------------------------------
// Projection GEMM: Out[n][j] = sum_d G[n][d]*W[j][d]
// z=0: Wq -> g_Q (scaled by beta*log2e), z=1: Wk -> g_K
// Block tile 128x128, k-stage 32, 256 threads (warps 2M x 4N, warp tile 64x32).
// Smem tiles: [row][granule16B] with granule ^= (row&7) swizzle; row = 8 granules.
// ---------------------------------------------------------------------------
__global__ __launch_bounds__(256) void proj_tc(const float* __restrict__ G,
                                               const float* __restrict__ Wq,
                                               const float* __restrict__ Wk) {
    __shared__ uint32_t As[128 * 32];
    __shared__ uint32_t Bs[128 * 32];

    const int z = blockIdx.z;
    const float* __restrict__ W = z ? Wk : Wq;
    float* __restrict__ Out = z ? g_K : g_Q;
    const float scale = z ? 1.0f : 0.18033688011112042f;  // beta*log2(e)

    const int bm = blockIdx.y * 128, bn = blockIdx.x * 128;
    const int tid = threadIdx.x, lane = tid & 31, wid = tid >> 5;
    const int wm = wid >> 2, wn = wid & 3;
    const uint32_t As_b = smem_u32(As), Bs_b = smem_u32(Bs);

    const int lrow = tid >> 3, lg = tid & 7;   // loader: 32 rows x 8 granules / iter

    float4 pa[4], pb[4];
#pragma unroll
    for (int i = 0; i < 4; i++) {
        int row = i * 32 + lrow;
        pa[i] = *(const float4*)&G[(size_t)(bm + row) * D_DIM + lg * 4];
        pb[i] = *(const float4*)&W[(size_t)(bn + row) * D_DIM + lg * 4];
    }

    float c[4][4][4];
#pragma unroll
    for (int mf = 0; mf < 4; mf++)
#pragma unroll
        for (int nf = 0; nf < 4; nf++)
#pragma unroll
            for (int q = 0; q < 4; q++) c[mf][nf][q] = 0.f;

    for (int s = 0; s < 24; s++) {
        // store prefetched stage
#pragma unroll
        for (int i = 0; i < 4; i++) {
            int row = i * 32 + lrow;
            int o = row * 8 + (lg ^ (row & 7));
            ((uint4*)As)[o] = make_uint4(f2tf(pa[i].x), f2tf(pa[i].y), f2tf(pa[i].z), f2tf(pa[i].w));
            ((uint4*)Bs)[o] = make_uint4(f2tf(pb[i].x), f2tf(pb[i].y), f2tf(pb[i].z), f2tf(pb[i].w));
        }
        __syncthreads();

        if (s < 23) {
            const int kt = (s + 1) * 32;
#pragma unroll
            for (int i = 0; i < 4; i++) {
                int row = i * 32 + lrow;
                pa[i] = *(const float4*)&G[(size_t)(bm + row) * D_DIM + kt + lg * 4];
                pb[i] = *(const float4*)&W[(size_t)(bn + row) * D_DIM + kt + lg * 4];
            }
        }

        const int mlo = (lane >> 3) & 1, mhi = lane >> 4, r8 = lane & 7;
#pragma unroll
        for (int j = 0; j < 4; j++) {
            uint32_t a[4][4];
#pragma unroll
            for (int mf = 0; mf < 4; mf++) {
                int row = wm * 64 + mf * 16 + mlo * 8 + r8;
                int g = 2 * j + mhi;
                ldmx4(a[mf], As_b + (uint32_t)(row * 8 + (g ^ (row & 7))) * 16);
            }
#pragma unroll
            for (int p = 0; p < 2; p++) {
                uint32_t b[4];
                int row = wn * 32 + p * 16 + mhi * 8 + r8;
                int g = 2 * j + mlo;
                ldmx4(b, Bs_b + (uint32_t)(row * 8 + (g ^ (row & 7))) * 16);
#pragma unroll
                for (int mf = 0; mf < 4; mf++) {
                    mma_tf32(c[mf][2 * p],     a[mf], b[0], b[1]);
                    mma_tf32(c[mf][2 * p + 1], a[mf], b[2], b[3]);
                }
            }
        }
        __syncthreads();
    }

    // store C
#pragma unroll
    for (int mf = 0; mf < 4; mf++) {
        int row = bm + wm * 64 + mf * 16 + (lane >> 2);
#pragma unroll
        for (int nf = 0; nf < 4; nf++) {
            int col = bn + wn * 32 + nf * 8 + 2 * (lane & 3);
            *(float2*)&Out[(size_t)row * HY + col] =
                make_float2(c[mf][nf][0] * scale, c[mf][nf][1] * scale);
            *(float2*)&Out[(size_t)(row + 8) * HY + col] =
                make_float2(c[mf][nf][2] * scale, c[mf][nf][3] * scale);
        }
    }
}

// ---------------------------------------------------------------------------
// Attention LSE: block = (64 q rows, head). 4 warps; warp w owns q rows w*16..+15.
// S tile per iter: 64q x 128k via mma tf32. Online log2-domain softmax in regs.
// Smem (dynamic): Qs [64][64] tf32, Ks [128][64] tf32 (single buffer + reg prefetch).
// ---------------------------------------------------------------------------
__global__ __launch_bounds__(128) void attn_tc() {
    extern __shared__ uint32_t smd[];
    uint32_t* Qs = smd;                 // 64*64
    uint32_t* Ks = smd + 64 * 64;       // 128*64
    __shared__ float red[64];

    const int h = blockIdx.y, qb = blockIdx.x, q0 = qb * 64;
    const int tid = threadIdx.x, lane = tid & 31, wid = tid >> 5;
    const uint32_t Qb = smem_u32(Qs), Kb = smem_u32(Ks);
    const int lrow = tid >> 4, lg = tid & 15;   // loader: 8 rows x 16 granules / iter

    // Load Q tile (rows 64 x 16 granules)
#pragma unroll
    for (int i = 0; i < 8; i++) {
        int row = i * 8 + lrow;
        float4 v = *(const float4*)&g_Q[(size_t)(q0 + row) * HY + h * 64 + lg * 4];
        ((uint4*)Qs)[row * 16 + (lg ^ (row & 7))] =
            make_uint4(f2tf(v.x), f2tf(v.y), f2tf(v.z), f2tf(v.w));
    }
    // Prefetch K tile 0
    float4 pk[16];
#pragma unroll
    for (int i = 0; i < 16; i++) {
        int row = i * 8 + lrow;
        pk[i] = *(const float4*)&g_K[(size_t)row * HY + h * 64 + lg * 4];
    }
    __syncthreads();

    // Preload all Q fragments (8 ksteps x 4 regs)
    const int mlo = (lane >> 3) & 1, mhi = lane >> 4, r8 = lane & 7;
    uint32_t QA[8][4];
#pragma unroll
    for (int j = 0; j < 8; j++) {
        int row = wid * 16 + mlo * 8 + r8;
        int g = 2 * j + mhi;
        ldmx4(QA[j], Qb + (uint32_t)(row * 16 + (g ^ (row & 7))) * 16);
    }

    float m0 = -1e30f, m1 = -1e30f, s0 = 0.f, s1 = 0.f;

    for (int t = 0; t < 16; t++) {
        // store prefetched K tile
#pragma unroll
        for (int i = 0; i < 16; i++) {
            int row = i * 8 + lrow;
            ((uint4*)Ks)[row * 16 + (lg ^ (row & 7))] =
                make_uint4(f2tf(pk[i].x), f2tf(pk[i].y), f2tf(pk[i].z), f2tf(pk[i].w));
        }
        __syncthreads();
        if (t < 15) {
#pragma unroll
            for (int i = 0; i < 16; i++) {
                int row = i * 8 + lrow;
                pk[i] = *(const float4*)&g_K[(size_t)((t + 1) * 128 + row) * HY + h * 64 + lg * 4];
            }
        }

        float c[16][4];
#pragma unroll
        for (int nf = 0; nf < 16; nf++)
#pragma unroll
            for (int q = 0; q < 4; q++) c[nf][q] = 0.f;

#pragma unroll
        for (int p = 0; p < 8; p++) {
#pragma unroll
            for (int j = 0; j < 8; j++) {
                uint32_t b[4];
                int row = p * 16 + mhi * 8 + r8;
                int g = 2 * j + mlo;
                ldmx4(b, Kb + (uint32_t)(row * 16 + (g ^ (row & 7))) * 16);
                mma_tf32(c[2 * p],     QA[j], b[0], b[1]);
                mma_tf32(c[2 * p + 1], QA[j], b[2], b[3]);
            }
        }

        // online softmax (log2 domain), rows r = lane>>2 and r+8
        float lm0 = -1e30f, lm1 = -1e30f;
#pragma unroll
        for (int nf = 0; nf < 16; nf++) {
            lm0 = fmaxf(lm0, fmaxf(c[nf][0], c[nf][1]));
            lm1 = fmaxf(lm1, fmaxf(c[nf][2], c[nf][3]));
        }
        lm0 = fmaxf(lm0, __shfl_xor_sync(0xffffffffu, lm0, 1));
        lm0 = fmaxf(lm0, __shfl_xor_sync(0xffffffffu, lm0, 2));
        lm1 = fmaxf(lm1, __shfl_xor_sync(0xffffffffu, lm1, 1));
        lm1 = fmaxf(lm1, __shfl_xor_sync(0xffffffffu, lm1, 2));
        float mn0 = fmaxf(m0, lm0), mn1 = fmaxf(m1, lm1);
        float p0 = 0.f, p1 = 0.f;
#pragma unroll
        for (int nf = 0; nf < 16; nf++) {
            p0 += exp2f(c[nf][0] - mn0) + exp2f(c[nf][1] - mn0);
            p1 += exp2f(c[nf][2] - mn1) + exp2f(c[nf][3] - mn1);
        }
        p0 += __shfl_xor_sync(0xffffffffu, p0, 1);
        p0 += __shfl_xor_sync(0xffffffffu, p0, 2);
        p1 += __shfl_xor_sync(0xffffffffu, p1, 1);
        p1 += __shfl_xor_sync(0xffffffffu, p1, 2);
        s0 = s0 * exp2f(m0 - mn0) + p0; m0 = mn0;
        s1 = s1 * exp2f(m1 - mn1) + p1; m1 = mn1;
        __syncthreads();
    }

    if ((lane & 3) == 0) {
        red[wid * 16 + (lane >> 2)]     = m0 + log2f(s0);
        red[wid * 16 + (lane >> 2) + 8] = m1 + log2f(s1);
    }
    __syncthreads();
    if (tid < 32) {
        float v = red[tid] + red[tid + 32];
#pragma unroll
        for (int off = 16; off > 0; off >>= 1)
            v += __shfl_xor_sync(0xffffffffu, v, off);
        if (tid == 0) g_partial[h * 32 + qb] = v;
    }
}

// ---------------------------------------------------------------------------
__global__ __launch_bounds__(128) void final_reduce_kernel(float* __restrict__ out) {
    __shared__ float sh[128];
    const int tid = threadIdx.x;
    sh[tid] = g_partial[tid] + g_partial[tid + 128] + g_partial[tid + 256];
    __syncthreads();
    for (int off = 64; off > 0; off >>= 1) {
        if (tid < off) sh[tid] += sh[tid + off];
        __syncthreads();
    }
    // lse_ln = ln2 * lse2 ; total * (-1/beta) = -8
    if (tid == 0) out[0] = -5.545177444479562f * sh[0];   // -8*ln(2)
}

// ---------------------------------------------------------------------------
extern "C" void kernel_launch(void* const* d_in, const int* in_sizes, int n_in,
                              void* d_out, int out_size) {
    const float* g  = (const float*)d_in[0];
    const float* Wq = (const float*)d_in[1];
    const float* Wk = (const float*)d_in[2];
    float* out = (float*)d_out;

    cudaFuncSetAttribute(attn_tc, cudaFuncAttributeMaxDynamicSharedMemorySize, 49152);

    proj_tc<<<dim3(6, 16, 2), 256>>>(g, Wq, Wk);
    attn_tc<<<dim3(32, H_HEADS), 128, 49152>>>();
    final_reduce_kernel<<<1, 128>>>(out);
}

// round 6
// speedup vs baseline: 4.8833x; 2.0216x over previous
#include <cuda_runtime.h>
#include <cstdint>
#include <math.h>

#define N_TOK 2048
#define D_DIM 768
#define HY 768
#define H_HEADS 12

// Scratch (allocation-free rule: device globals)
__device__ float g_gr[N_TOK * D_DIM];    // tf32-rounded g
__device__ float g_wqr[HY * D_DIM];      // tf32-rounded Wq
__device__ float g_wkr[HY * D_DIM];      // tf32-rounded Wk
__device__ float g_Q[N_TOK * HY];        // tf32, scaled by beta*log2e
__device__ float g_K[N_TOK * HY];        // tf32
__device__ float g_partial[H_HEADS * 32];

// ---------------------------------------------------------------------------
__device__ __forceinline__ uint32_t smem_u32(const void* p) {
    uint32_t a;
    asm("{ .reg .u64 t; cvta.to.shared.u64 t, %1; cvt.u32.u64 %0, t; }"
        : "=r"(a) : "l"(p));
    return a;
}
__device__ __forceinline__ uint32_t f2tf(float x) {   // round-to-nearest tf32
    uint32_t r;
    asm("cvt.rna.tf32.f32 %0, %1;" : "=r"(r) : "f"(x));
    return r;
}
__device__ __forceinline__ void ldmx4(uint32_t r[4], uint32_t addr) {
    asm volatile("ldmatrix.sync.aligned.m8n8.x4.shared.b16 {%0,%1,%2,%3}, [%4];"
                 : "=r"(r[0]), "=r"(r[1]), "=r"(r[2]), "=r"(r[3]) : "r"(addr));
}
__device__ __forceinline__ void mma_tf32(float c[4], const uint32_t a[4],
                                         uint32_t b0, uint32_t b1) {
    asm volatile(
        "mma.sync.aligned.m16n8k8.row.col.f32.tf32.tf32.f32 "
        "{%0,%1,%2,%3}, {%4,%5,%6,%7}, {%8,%9}, {%0,%1,%2,%3};"
        : "+f"(c[0]), "+f"(c[1]), "+f"(c[2]), "+f"(c[3])
        : "r"(a[0]), "r"(a[1]), "r"(a[2]), "r"(a[3]), "r"(b0), "r"(b1));
}
#define CP_ASYNC16(dst, src) \
    asm volatile("cp.async.cg.shared.global [%0], [%1], 16;" :: "r"(dst), "l"(src))
#define CP_COMMIT() asm volatile("cp.async.commit_group;" ::: "memory")
#define CP_WAIT1()  asm volatile("cp.async.wait_group 1;" ::: "memory")

// ---------------------------------------------------------------------------
// Pre-round all inputs to tf32 (so cp.async paths need no conversion).
// ---------------------------------------------------------------------------
__global__ __launch_bounds__(256) void round_inputs(const float* __restrict__ g,
                                                    const float* __restrict__ wq,
                                                    const float* __restrict__ wk) {
    const int stride = gridDim.x * blockDim.x;
    const int i0 = blockIdx.x * blockDim.x + threadIdx.x;
    const int NG = N_TOK * D_DIM / 4, NW = HY * D_DIM / 4;
    const float4* g4  = (const float4*)g;
    const float4* wq4 = (const float4*)wq;
    const float4* wk4 = (const float4*)wk;
    float4* og = (float4*)g_gr;
    float4* oq = (float4*)g_wqr;
    float4* ok = (float4*)g_wkr;
    for (int t = i0; t < NG; t += stride) {
        float4 v = g4[t];
        og[t] = make_float4(__uint_as_float(f2tf(v.x)), __uint_as_float(f2tf(v.y)),
                            __uint_as_float(f2tf(v.z)), __uint_as_float(f2tf(v.w)));
    }
    for (int t = i0; t < NW; t += stride) {
        float4 v = wq4[t];
        oq[t] = make_float4(__uint_as_float(f2tf(v.x)), __uint_as_float(f2tf(v.y)),
                            __uint_as_float(f2tf(v.z)), __uint_as_float(f2tf(v.w)));
        float4 w = wk4[t];
        ok[t] = make_float4(__uint_as_float(f2tf(w.x)), __uint_as_float(f2tf(w.y)),
                            __uint_as_float(f2tf(w.z)), __uint_as_float(f2tf(w.w)));
    }
}

// ---------------------------------------------------------------------------
// Projection: Out[n][j] = sum_d G[n][d]*W[j][d].  z=0: Wq->g_Q (*beta*log2e).
// Tile 128x64, k-stage 32, 128 threads (2x2 warps, warp tile 64x32).
// cp.async 2-stage pipeline from pre-rounded inputs.
// Dynamic smem 48KB: As[2][128*32] @0/16K, Bs[2][64*32] @32K/40K (bytes).
// ---------------------------------------------------------------------------
__global__ __launch_bounds__(128) void proj_tc() {
    extern __shared__ uint32_t smd[];
    const uint32_t sb = smem_u32(smd);

    const int z = blockIdx.z;
    const float* __restrict__ W = z ? g_wkr : g_wqr;
    float* __restrict__ Out = z ? g_K : g_Q;
    const float scale = z ? 1.0f : 0.18033688011112042f;  // beta*log2(e)

    const int bm = blockIdx.y * 128, bn = blockIdx.x * 64;
    const int tid = threadIdx.x, lane = tid & 31, wid = tid >> 5;
    const int wm = wid >> 1, wn = wid & 1;
    const int lrow = tid >> 3, lg = tid & 7;   // loader: 16 rows x 8 granules

    auto issue = [&](int s, int buf) {
        const int kt = s * 32;
        const uint32_t Ab = sb + buf * 16384;
        const uint32_t Bb = sb + 32768 + buf * 8192;
#pragma unroll
        for (int i = 0; i < 8; i++) {
            int row = i * 16 + lrow;
            CP_ASYNC16(Ab + (uint32_t)(row * 8 + (lg ^ (row & 7))) * 16,
                       &g_gr[(size_t)(bm + row) * D_DIM + kt + lg * 4]);
        }
#pragma unroll
        for (int i = 0; i < 4; i++) {
            int row = i * 16 + lrow;
            CP_ASYNC16(Bb + (uint32_t)(row * 8 + (lg ^ (row & 7))) * 16,
                       &W[(size_t)(bn + row) * D_DIM + kt + lg * 4]);
        }
    };

    issue(0, 0); CP_COMMIT();
    issue(1, 1); CP_COMMIT();

    float c[4][4][4];
#pragma unroll
    for (int mf = 0; mf < 4; mf++)
#pragma unroll
        for (int nf = 0; nf < 4; nf++)
#pragma unroll
            for (int q = 0; q < 4; q++) c[mf][nf][q] = 0.f;

    const int mlo = (lane >> 3) & 1, mhi = lane >> 4, r8 = lane & 7;

    for (int s = 0; s < 24; s++) {
        CP_WAIT1();
        __syncthreads();
        const int buf = s & 1;
        const uint32_t Ab = sb + buf * 16384;
        const uint32_t Bb = sb + 32768 + buf * 8192;
#pragma unroll
        for (int j = 0; j < 4; j++) {
            uint32_t a[4][4];
#pragma unroll
            for (int mf = 0; mf < 4; mf++) {
                int row = wm * 64 + mf * 16 + mlo * 8 + r8;
                int g = 2 * j + mhi;
                ldmx4(a[mf], Ab + (uint32_t)(row * 8 + (g ^ (row & 7))) * 16);
            }
#pragma unroll
            for (int p = 0; p < 2; p++) {
                uint32_t b[4];
                int row = wn * 32 + p * 16 + mhi * 8 + r8;
                int g = 2 * j + mlo;
                ldmx4(b, Bb + (uint32_t)(row * 8 + (g ^ (row & 7))) * 16);
#pragma unroll
                for (int mf = 0; mf < 4; mf++) {
                    mma_tf32(c[mf][2 * p],     a[mf], b[0], b[1]);
                    mma_tf32(c[mf][2 * p + 1], a[mf], b[2], b[3]);
                }
            }
        }
        __syncthreads();
        if (s + 2 < 24) issue(s + 2, buf);
        CP_COMMIT();
    }

    // store C, pre-rounded to tf32 (attn consumes without conversion)
#pragma unroll
    for (int mf = 0; mf < 4; mf++) {
        int row = bm + wm * 64 + mf * 16 + (lane >> 2);
#pragma unroll
        for (int nf = 0; nf < 4; nf++) {
            int col = bn + wn * 32 + nf * 8 + 2 * (lane & 3);
            *(float2*)&Out[(size_t)row * HY + col] = make_float2(
                __uint_as_float(f2tf(c[mf][nf][0] * scale)),
                __uint_as_float(f2tf(c[mf][nf][1] * scale)));
            *(float2*)&Out[(size_t)(row + 8) * HY + col] = make_float2(
                __uint_as_float(f2tf(c[mf][nf][2] * scale)),
                __uint_as_float(f2tf(c[mf][nf][3] * scale)));
        }
    }
}

// ---------------------------------------------------------------------------
// Attention LSE: block = (64 q rows, head). 4 warps; warp w owns rows w*16..+15.
// K tiles of 64 rows, cp.async 2-stage. Online log2-domain softmax with
// tile-skip: tiles > 40 log2-units below the running max contribute < 2^-29
// relative and are skipped (no exp work). Per-lane partial s, reduced at end.
// Dynamic smem 48KB: Qs @0 (16KB), Ks[2] @16K/32K.
// ---------------------------------------------------------------------------
__global__ __launch_bounds__(128) void attn_tc() {
    extern __shared__ uint32_t smd[];
    const uint32_t sb = smem_u32(smd);
    __shared__ float red[64];

    const int h = blockIdx.y, qb = blockIdx.x, q0 = qb * 64;
    const int tid = threadIdx.x, lane = tid & 31, wid = tid >> 5;
    const int lrow = tid >> 4, lg = tid & 15;   // loader: 8 rows x 16 granules

    // issue Q (group 0)
#pragma unroll
    for (int i = 0; i < 8; i++) {
        int row = i * 8 + lrow;
        CP_ASYNC16(sb + (uint32_t)(row * 16 + (lg ^ (row & 7))) * 16,
                   &g_Q[(size_t)(q0 + row) * HY + h * 64 + lg * 4]);
    }
    CP_COMMIT();

    auto issueK = [&](int t, int buf) {
        const uint32_t Kb = sb + 16384 + buf * 16384;
#pragma unroll
        for (int i = 0; i < 8; i++) {
            int row = i * 8 + lrow;
            CP_ASYNC16(Kb + (uint32_t)(row * 16 + (lg ^ (row & 7))) * 16,
                       &g_K[(size_t)(t * 64 + row) * HY + h * 64 + lg * 4]);
        }
    };
    issueK(0, 0); CP_COMMIT();
    issueK(1, 1); CP_COMMIT();

    CP_WAIT1();          // Q + K0 complete
    __syncthreads();

    // preload Q fragments (8 ksteps x 4 regs)
    const int mlo = (lane >> 3) & 1, mhi = lane >> 4, r8 = lane & 7;
    uint32_t QA[8][4];
#pragma unroll
    for (int j = 0; j < 8; j++) {
        int row = wid * 16 + mlo * 8 + r8;
        int g = 2 * j + mhi;
        ldmx4(QA[j], sb + (uint32_t)(row * 16 + (g ^ (row & 7))) * 16);
    }

    float m0 = -1e30f, m1 = -1e30f, s0 = 0.f, s1 = 0.f;

    for (int t = 0; t < 32; t++) {
        if (t > 0) { CP_WAIT1(); __syncthreads(); }
        const int buf = t & 1;
        const uint32_t Kb = sb + 16384 + buf * 16384;

        float c[8][4];
#pragma unroll
        for (int nf = 0; nf < 8; nf++)
#pragma unroll
            for (int q = 0; q < 4; q++) c[nf][q] = 0.f;

#pragma unroll
        for (int p = 0; p < 4; p++) {
#pragma unroll
            for (int j = 0; j < 8; j++) {
                uint32_t b[4];
                int row = p * 16 + mhi * 8 + r8;
                int g = 2 * j + mlo;
                ldmx4(b, Kb + (uint32_t)(row * 16 + (g ^ (row & 7))) * 16);
                mma_tf32(c[2 * p],     QA[j], b[0], b[1]);
                mma_tf32(c[2 * p + 1], QA[j], b[2], b[3]);
            }
        }
        __syncthreads();
        if (t + 2 < 32) issueK(t + 2, buf);
        CP_COMMIT();

        // tile max per row group (lanes converged here)
        float lm0 = -1e30f, lm1 = -1e30f;
#pragma unroll
        for (int nf = 0; nf < 8; nf++) {
            lm0 = fmaxf(lm0, fmaxf(c[nf][0], c[nf][1]));
            lm1 = fmaxf(lm1, fmaxf(c[nf][2], c[nf][3]));
        }
        lm0 = fmaxf(lm0, __shfl_xor_sync(0xffffffffu, lm0, 1));
        lm0 = fmaxf(lm0, __shfl_xor_sync(0xffffffffu, lm0, 2));
        lm1 = fmaxf(lm1, __shfl_xor_sync(0xffffffffu, lm1, 1));
        lm1 = fmaxf(lm1, __shfl_xor_sync(0xffffffffu, lm1, 2));

        // skip tiles that cannot contribute (no shfl inside branches)
        if (lm0 >= m0 - 40.f) {
            float mn = fmaxf(m0, lm0);
            float p = 0.f;
#pragma unroll
            for (int nf = 0; nf < 8; nf++)
                p += exp2f(c[nf][0] - mn) + exp2f(c[nf][1] - mn);
            s0 = s0 * exp2f(m0 - mn) + p;   // per-lane partial sum
            m0 = mn;
        }
        if (lm1 >= m1 - 40.f) {
            float mn = fmaxf(m1, lm1);
            float p = 0.f;
#pragma unroll
            for (int nf = 0; nf < 8; nf++)
                p += exp2f(c[nf][2] - mn) + exp2f(c[nf][3] - mn);
            s1 = s1 * exp2f(m1 - mn) + p;
            m1 = mn;
        }
    }

    // reduce per-lane partials over the 4-lane row group (converged now)
    s0 += __shfl_xor_sync(0xffffffffu, s0, 1);
    s0 += __shfl_xor_sync(0xffffffffu, s0, 2);
    s1 += __shfl_xor_sync(0xffffffffu, s1, 1);
    s1 += __shfl_xor_sync(0xffffffffu, s1, 2);

    if ((lane & 3) == 0) {
        red[wid * 16 + (lane >> 2)]     = m0 + log2f(s0);
        red[wid * 16 + (lane >> 2) + 8] = m1 + log2f(s1);
    }
    __syncthreads();
    if (tid < 32) {
        float v = red[tid] + red[tid + 32];
#pragma unroll
        for (int off = 16; off > 0; off >>= 1)
            v += __shfl_xor_sync(0xffffffffu, v, off);
        if (tid == 0) g_partial[h * 32 + qb] = v;
    }
}

// ---------------------------------------------------------------------------
__global__ __launch_bounds__(128) void final_reduce_kernel(float* __restrict__ out) {
    __shared__ float sh[128];
    const int tid = threadIdx.x;
    sh[tid] = g_partial[tid] + g_partial[tid + 128] + g_partial[tid + 256];
    __syncthreads();
    for (int off = 64; off > 0; off >>= 1) {
        if (tid < off) sh[tid] += sh[tid + off];
        __syncthreads();
    }
    if (tid == 0) out[0] = -5.545177444479562f * sh[0];   // -8*ln(2)
}

// ---------------------------------------------------------------------------
extern "C" void kernel_launch(void* const* d_in, const int* in_sizes, int n_in,
                              void* d_out, int out_size) {
    const float* g  = (const float*)d_in[0];
    const float* Wq = (const float*)d_in[1];
    const float* Wk = (const float*)d_in[2];
    float* out = (float*)d_out;

    cudaFuncSetAttribute(proj_tc, cudaFuncAttributeMaxDynamicSharedMemorySize, 49152);
    cudaFuncSetAttribute(attn_tc, cudaFuncAttributeMaxDynamicSharedMemorySize, 49152);

    round_inputs<<<296, 256>>>(g, Wq, Wk);
    proj_tc<<<dim3(12, 16, 2), 128, 49152>>>();
    attn_tc<<<dim3(32, H_HEADS), 128, 49152>>>();
    final_reduce_kernel<<<1, 128>>>(out);
}

// round 7
// speedup vs baseline: 7.1278x; 1.4596x over previous
#include <cuda_runtime.h>
#include <cuda_bf16.h>
#include <cstdint>
#include <math.h>

#define N_TOK 2048
#define D_DIM 768
#define HY 768
#define H_HEADS 12

// Scratch (allocation-free rule: device globals)
__device__ __nv_bfloat16 g_gr[N_TOK * D_DIM];   // bf16-rounded g
__device__ __nv_bfloat16 g_wqr[HY * D_DIM];     // bf16-rounded Wq
__device__ __nv_bfloat16 g_wkr[HY * D_DIM];     // bf16-rounded Wk
__device__ __nv_bfloat16 g_Q[N_TOK * HY];       // bf16, scaled by beta*log2e
__device__ __nv_bfloat16 g_K[N_TOK * HY];       // bf16
__device__ float g_partial[H_HEADS * 32];
__device__ int   g_count;                       // last-block counter (self-resetting)

// ---------------------------------------------------------------------------
__device__ __forceinline__ uint32_t smem_u32(const void* p) {
    uint32_t a;
    asm("{ .reg .u64 t; cvta.to.shared.u64 t, %1; cvt.u32.u64 %0, t; }"
        : "=r"(a) : "l"(p));
    return a;
}
__device__ __forceinline__ uint32_t pack_bf2(float x, float y) {
    __nv_bfloat162 h = __floats2bfloat162_rn(x, y);
    return *reinterpret_cast<uint32_t*>(&h);
}
__device__ __forceinline__ void ldmx4(uint32_t r[4], uint32_t addr) {
    asm volatile("ldmatrix.sync.aligned.m8n8.x4.shared.b16 {%0,%1,%2,%3}, [%4];"
                 : "=r"(r[0]), "=r"(r[1]), "=r"(r[2]), "=r"(r[3]) : "r"(addr));
}
__device__ __forceinline__ void mma_bf16(float c[4], const uint32_t a[4],
                                         uint32_t b0, uint32_t b1) {
    asm volatile(
        "mma.sync.aligned.m16n8k16.row.col.f32.bf16.bf16.f32 "
        "{%0,%1,%2,%3}, {%4,%5,%6,%7}, {%8,%9}, {%0,%1,%2,%3};"
        : "+f"(c[0]), "+f"(c[1]), "+f"(c[2]), "+f"(c[3])
        : "r"(a[0]), "r"(a[1]), "r"(a[2]), "r"(a[3]), "r"(b0), "r"(b1));
}
#define CP_ASYNC16(dst, src) \
    asm volatile("cp.async.cg.shared.global [%0], [%1], 16;" :: "r"(dst), "l"(src))
#define CP_COMMIT() asm volatile("cp.async.commit_group;" ::: "memory")
#define CP_WAIT1()  asm volatile("cp.async.wait_group 1;" ::: "memory")

// ---------------------------------------------------------------------------
// Pre-round all inputs to bf16.
// ---------------------------------------------------------------------------
__global__ __launch_bounds__(256) void round_inputs(const float* __restrict__ g,
                                                    const float* __restrict__ wq,
                                                    const float* __restrict__ wk) {
    const int stride = gridDim.x * blockDim.x;
    const int i0 = blockIdx.x * blockDim.x + threadIdx.x;
    const int NG = N_TOK * D_DIM / 4, NW = HY * D_DIM / 4;
    const float4* g4  = (const float4*)g;
    const float4* wq4 = (const float4*)wq;
    const float4* wk4 = (const float4*)wk;
    uint2* og = (uint2*)g_gr;
    uint2* oq = (uint2*)g_wqr;
    uint2* ok = (uint2*)g_wkr;
    for (int t = i0; t < NG; t += stride) {
        float4 v = g4[t];
        og[t] = make_uint2(pack_bf2(v.x, v.y), pack_bf2(v.z, v.w));
    }
    for (int t = i0; t < NW; t += stride) {
        float4 v = wq4[t];
        oq[t] = make_uint2(pack_bf2(v.x, v.y), pack_bf2(v.z, v.w));
        float4 w = wk4[t];
        ok[t] = make_uint2(pack_bf2(w.x, w.y), pack_bf2(w.z, w.w));
    }
}

// ---------------------------------------------------------------------------
// Projection: Out[n][j] = sum_d G[n][d]*W[j][d].  z=0: Wq->g_Q (*beta*log2e).
// Tile 128x64, k-stage 64 bf16 (128B/row, 8 granules), 12 stages, 128 threads
// (2x2 warps, warp tile 64x32), cp.async 2-stage pipeline.
// Dynamic smem 48KB: As[2] @0/16K (16KB each), Bs[2] @32K/40K (8KB each).
// ---------------------------------------------------------------------------
__global__ __launch_bounds__(128) void proj_tc() {
    extern __shared__ uint32_t smd[];
    const uint32_t sb = smem_u32(smd);

    const int z = blockIdx.z;
    const __nv_bfloat16* __restrict__ W = z ? g_wkr : g_wqr;
    __nv_bfloat16* __restrict__ Out = z ? g_K : g_Q;
    const float scale = z ? 1.0f : 0.18033688011112042f;  // beta*log2(e)

    const int bm = blockIdx.y * 128, bn = blockIdx.x * 64;
    const int tid = threadIdx.x, lane = tid & 31, wid = tid >> 5;
    const int wm = wid >> 1, wn = wid & 1;
    const int lrow = tid >> 3, lg = tid & 7;   // loader: 16 rows x 8 granules(16B)

    auto issue = [&](int s, int buf) {
        const int kt = s * 64;
        const uint32_t Ab = sb + buf * 16384;
        const uint32_t Bb = sb + 32768 + buf * 8192;
#pragma unroll
        for (int i = 0; i < 8; i++) {
            int row = i * 16 + lrow;
            CP_ASYNC16(Ab + (uint32_t)(row * 8 + (lg ^ (row & 7))) * 16,
                       &g_gr[(size_t)(bm + row) * D_DIM + kt + lg * 8]);
        }
#pragma unroll
        for (int i = 0; i < 4; i++) {
            int row = i * 16 + lrow;
            CP_ASYNC16(Bb + (uint32_t)(row * 8 + (lg ^ (row & 7))) * 16,
                       &W[(size_t)(bn + row) * D_DIM + kt + lg * 8]);
        }
    };

    issue(0, 0); CP_COMMIT();
    issue(1, 1); CP_COMMIT();

    float c[4][4][4];
#pragma unroll
    for (int mf = 0; mf < 4; mf++)
#pragma unroll
        for (int nf = 0; nf < 4; nf++)
#pragma unroll
            for (int q = 0; q < 4; q++) c[mf][nf][q] = 0.f;

    const int mlo = (lane >> 3) & 1, mhi = lane >> 4, r8 = lane & 7;

    for (int s = 0; s < 12; s++) {
        CP_WAIT1();
        __syncthreads();
        const int buf = s & 1;
        const uint32_t Ab = sb + buf * 16384;
        const uint32_t Bb = sb + 32768 + buf * 8192;
#pragma unroll
        for (int ks = 0; ks < 4; ks++) {
            uint32_t a[4][4];
#pragma unroll
            for (int mf = 0; mf < 4; mf++) {
                int row = wm * 64 + mf * 16 + mlo * 8 + r8;
                int g = 2 * ks + mhi;
                ldmx4(a[mf], Ab + (uint32_t)(row * 8 + (g ^ (row & 7))) * 16);
            }
#pragma unroll
            for (int p = 0; p < 2; p++) {
                uint32_t b[4];
                int row = wn * 32 + p * 16 + mhi * 8 + r8;
                int g = 2 * ks + mlo;
                ldmx4(b, Bb + (uint32_t)(row * 8 + (g ^ (row & 7))) * 16);
#pragma unroll
                for (int mf = 0; mf < 4; mf++) {
                    mma_bf16(c[mf][2 * p],     a[mf], b[0], b[1]);
                    mma_bf16(c[mf][2 * p + 1], a[mf], b[2], b[3]);
                }
            }
        }
        __syncthreads();
        if (s + 2 < 12) issue(s + 2, buf);
        CP_COMMIT();
    }

    // store C as bf16 (attn consumes without conversion)
#pragma unroll
    for (int mf = 0; mf < 4; mf++) {
        int row = bm + wm * 64 + mf * 16 + (lane >> 2);
#pragma unroll
        for (int nf = 0; nf < 4; nf++) {
            int col = bn + wn * 32 + nf * 8 + 2 * (lane & 3);
            *(uint32_t*)&Out[(size_t)row * HY + col] =
                pack_bf2(c[mf][nf][0] * scale, c[mf][nf][1] * scale);
            *(uint32_t*)&Out[(size_t)(row + 8) * HY + col] =
                pack_bf2(c[mf][nf][2] * scale, c[mf][nf][3] * scale);
        }
    }
}

// ---------------------------------------------------------------------------
// Attention LSE: block = (64 q rows, head). 4 warps; warp w owns rows w*16..+15.
// K tiles of 128 rows (16KB bf16), cp.async 2-stage. Online log2-domain softmax
// with tile-skip (>40 log2-units below running max -> skipped).
// Last block also performs the final 384-partial reduction (deterministic order)
// and resets the counter for graph replays.
// Dynamic smem 40KB: Qs @0 (8KB), Ks[2] @8K/24K (16KB each).
// ---------------------------------------------------------------------------
__global__ __launch_bounds__(128) void attn_tc(float* __restrict__ out) {
    extern __shared__ uint32_t smd[];
    const uint32_t sb = smem_u32(smd);
    __shared__ float red[64];
    __shared__ int last;

    const int h = blockIdx.y, qb = blockIdx.x, q0 = qb * 64;
    const int tid = threadIdx.x, lane = tid & 31, wid = tid >> 5;
    const int lrow = tid >> 3, lg = tid & 7;   // loader: 16 rows x 8 granules

    // issue Q (64 rows)
#pragma unroll
    for (int i = 0; i < 4; i++) {
        int row = i * 16 + lrow;
        CP_ASYNC16(sb + (uint32_t)(row * 8 + (lg ^ (row & 7))) * 16,
                   &g_Q[(size_t)(q0 + row) * HY + h * 64 + lg * 8]);
    }
    CP_COMMIT();

    auto issueK = [&](int t, int buf) {
        const uint32_t Kb = sb + 8192 + buf * 16384;
#pragma unroll
        for (int i = 0; i < 8; i++) {
            int row = i * 16 + lrow;
            CP_ASYNC16(Kb + (uint32_t)(row * 8 + (lg ^ (row & 7))) * 16,
                       &g_K[(size_t)(t * 128 + row) * HY + h * 64 + lg * 8]);
        }
    };
    issueK(0, 0); CP_COMMIT();
    issueK(1, 1); CP_COMMIT();

    CP_WAIT1();          // Q + K0 complete
    __syncthreads();

    // preload Q fragments (4 ksteps x 4 regs)
    const int mlo = (lane >> 3) & 1, mhi = lane >> 4, r8 = lane & 7;
    uint32_t QA[4][4];
#pragma unroll
    for (int ks = 0; ks < 4; ks++) {
        int row = wid * 16 + mlo * 8 + r8;
        int g = 2 * ks + mhi;
        ldmx4(QA[ks], sb + (uint32_t)(row * 8 + (g ^ (row & 7))) * 16);
    }

    float m0 = -1e30f, m1 = -1e30f, s0 = 0.f, s1 = 0.f;

    for (int t = 0; t < 16; t++) {
        if (t > 0) { CP_WAIT1(); __syncthreads(); }
        const uint32_t Kb = sb + 8192 + (t & 1) * 16384;

        float c[16][4];
#pragma unroll
        for (int nf = 0; nf < 16; nf++)
#pragma unroll
            for (int q = 0; q < 4; q++) c[nf][q] = 0.f;

#pragma unroll
        for (int ks = 0; ks < 4; ks++) {
#pragma unroll
            for (int p = 0; p < 8; p++) {
                uint32_t b[4];
                int row = p * 16 + mhi * 8 + r8;
                int g = 2 * ks + mlo;
                ldmx4(b, Kb + (uint32_t)(row * 8 + (g ^ (row & 7))) * 16);
                mma_bf16(c[2 * p],     QA[ks], b[0], b[1]);
                mma_bf16(c[2 * p + 1], QA[ks], b[2], b[3]);
            }
        }
        __syncthreads();
        if (t + 2 < 16) issueK(t + 2, t & 1);
        CP_COMMIT();

        // tile max per row group (lanes converged here)
        float lm0 = -1e30f, lm1 = -1e30f;
#pragma unroll
        for (int nf = 0; nf < 16; nf++) {
            lm0 = fmaxf(lm0, fmaxf(c[nf][0], c[nf][1]));
            lm1 = fmaxf(lm1, fmaxf(c[nf][2], c[nf][3]));
        }
        lm0 = fmaxf(lm0, __shfl_xor_sync(0xffffffffu, lm0, 1));
        lm0 = fmaxf(lm0, __shfl_xor_sync(0xffffffffu, lm0, 2));
        lm1 = fmaxf(lm1, __shfl_xor_sync(0xffffffffu, lm1, 1));
        lm1 = fmaxf(lm1, __shfl_xor_sync(0xffffffffu, lm1, 2));

        // skip tiles that cannot contribute (no shfl inside branches)
        if (lm0 >= m0 - 40.f) {
            float mn = fmaxf(m0, lm0);
            float p = 0.f;
#pragma unroll
            for (int nf = 0; nf < 16; nf++)
                p += exp2f(c[nf][0] - mn) + exp2f(c[nf][1] - mn);
            s0 = s0 * exp2f(m0 - mn) + p;   // per-lane partial sum
            m0 = mn;
        }
        if (lm1 >= m1 - 40.f) {
            float mn = fmaxf(m1, lm1);
            float p = 0.f;
#pragma unroll
            for (int nf = 0; nf < 16; nf++)
                p += exp2f(c[nf][2] - mn) + exp2f(c[nf][3] - mn);
            s1 = s1 * exp2f(m1 - mn) + p;
            m1 = mn;
        }
    }

    // reduce per-lane partials over the 4-lane row group
    s0 += __shfl_xor_sync(0xffffffffu, s0, 1);
    s0 += __shfl_xor_sync(0xffffffffu, s0, 2);
    s1 += __shfl_xor_sync(0xffffffffu, s1, 1);
    s1 += __shfl_xor_sync(0xffffffffu, s1, 2);

    if ((lane & 3) == 0) {
        red[wid * 16 + (lane >> 2)]     = m0 + log2f(s0);
        red[wid * 16 + (lane >> 2) + 8] = m1 + log2f(s1);
    }
    __syncthreads();
    if (tid < 32) {
        float v = red[tid] + red[tid + 32];
#pragma unroll
        for (int off = 16; off > 0; off >>= 1)
            v += __shfl_xor_sync(0xffffffffu, v, off);
        if (tid == 0) g_partial[h * 32 + qb] = v;
    }

    // --- fused final reduction: last arriving block sums all 384 partials ---
    if (tid == 0) {
        __threadfence();
        last = (atomicAdd(&g_count, 1) == H_HEADS * 32 - 1);
    }
    __syncthreads();
    if (last) {
        __threadfence();
        float v = g_partial[tid] + g_partial[tid + 128] + g_partial[tid + 256];
#pragma unroll
        for (int off = 16; off > 0; off >>= 1)
            v += __shfl_xor_sync(0xffffffffu, v, off);
        if (lane == 0) red[wid] = v;
        __syncthreads();
        if (tid == 0) {
            out[0] = -5.545177444479562f * (red[0] + red[1] + red[2] + red[3]);
            g_count = 0;   // reset for next graph replay
        }
    }
}

// ---------------------------------------------------------------------------
extern "C" void kernel_launch(void* const* d_in, const int* in_sizes, int n_in,
                              void* d_out, int out_size) {
    const float* g  = (const float*)d_in[0];
    const float* Wq = (const float*)d_in[1];
    const float* Wk = (const float*)d_in[2];
    float* out = (float*)d_out;

    cudaFuncSetAttribute(proj_tc, cudaFuncAttributeMaxDynamicSharedMemorySize, 49152);
    cudaFuncSetAttribute(attn_tc, cudaFuncAttributeMaxDynamicSharedMemorySize, 40960);

    round_inputs<<<296, 256>>>(g, Wq, Wk);
    proj_tc<<<dim3(12, 16, 2), 128, 49152>>>();
    attn_tc<<<dim3(32, H_HEADS), 128, 40960>>>(out);
}